// round 7
// baseline (speedup 1.0000x reference)
#include <cuda_runtime.h>
#include <cuda_bf16.h>

// Output [B,2] = [p, 1-p], p = sigmoid(evs . fc3_w + fc3_b); evs depends only
// on the 4-qubit circuit (q_params, q_basis). CNN branch is dead code.
//
// R6: shorten the shfl dependency chain via circuit algebra.
//  - Pre-CNOT state is a product state: amp[i] = prod_w Wcol0_w[bit_w(i)],
//    W_w = U_layer0_w * U_basis_w. Replaces 8 chained GATE steps with
//    parallel shfl gathers + a 2-level complex product tree.
//  - Final CNOT chain is a basis permutation -> pushed into the measurement
//    coefficient index (lane-local int ops, off critical path).
//  - State mirrored in both 16-lane halves so the 4-round butterfly leaves
//    the full sum in EVERY lane (no final broadcast shfl).
// Chained shfl steps: 23 -> 11.

__global__ __launch_bounds__(512, 1)
void qhbc_kernel(const float* __restrict__ q_params,  // [2,4,3]
                 const float* __restrict__ q_basis,   // [4,3]
                 const float* __restrict__ fc3_w,     // [1,4]
                 const float* __restrict__ fc3_b,     // [1]
                 float4* __restrict__ out4,           // [B/2] of (p,q,p,q)
                 int n4) {
    const int tid  = threadIdx.x;
    const int lane = tid & 31;
    const int amp  = lane & 15;          // amplitude index (mirrored halves)

    // ---- All global loads up front ----
    // Gate slot = lane: 0..3 basis(w), 4..7 layer0(w), 8..11 layer1(w).
    const int w_ = lane & 3;
    const float* ang = (lane < 4) ? (q_basis + w_ * 3)
                                  : (q_params + (lane - 4) * 3);
    const float a0 = (lane < 12) ? ang[0] : 0.f;
    const float a1 = (lane < 12) ? ang[1] : 0.f;
    const float a2 = (lane < 12) ? ang[2] : 0.f;
    const float f0 = fc3_w[0], f1 = fc3_w[1], f2 = fc3_w[2], f3 = fc3_w[3];
    const float bias = fc3_b[0];

    // ---- Measurement coefficient with the FINAL CNOT chain folded in ----
    // CNOT(w): if control bit (8>>w) set, flip target bit (4>>w). Applied to
    // the coefficient index instead of the state (permutation invariance of
    // |amp|^2 sums). wire0->bit3 ... wire3->bit0.
    int j = amp;
    if (j & 8) j ^= 4;
    if (j & 4) j ^= 2;
    if (j & 2) j ^= 1;
    const float coef = ((j & 8) ? -f0 : f0) + ((j & 4) ? -f1 : f1)
                     + ((j & 2) ? -f2 : f2) + ((j & 1) ? -f3 : f3);

    // ---- Merged SU(2) gate U = Rz*Ry*Rx for this lane's slot ----
    // U = [[u0, u1], [-conj(u1), conj(u0)]]
    float sa, ca, sb, cb, sc, cc;
    __sincosf(0.5f * a0, &sa, &ca);   // Rx
    __sincosf(0.5f * a1, &sb, &cb);   // Ry
    __sincosf(0.5f * a2, &sc, &cc);   // Rz
    const float m00r =  cb * ca, m00i =  sb * sa;
    const float m01r = -sb * ca, m01i = -cb * sa;
    const float gu0r = cc * m00r + sc * m00i;   // u0.r
    const float gu0i = cc * m00i - sc * m00r;   // u0.i
    const float gu1r = cc * m01r + sc * m01i;   // u1.r
    const float gu1i = cc * m01i - sc * m01r;   // u1.i

    // ---- W_w = U_layer0_w * U_basis_w, column 0 (lanes 0..3 hold wire w) ----
    // basis gate = own (a1,b1); layer0 gate from lane w+4 = (a2,b2).
    // Wcol0 top    W0 = a2*a1 - b2*conj(b1)
    // Wcol0 bottom W1 = -(conj(b2)*a1 + conj(a2)*conj(b1))
    const float a2r = __shfl_down_sync(0xffffffffu, gu0r, 4);
    const float a2i = __shfl_down_sync(0xffffffffu, gu0i, 4);
    const float b2r = __shfl_down_sync(0xffffffffu, gu1r, 4);
    const float b2i = __shfl_down_sync(0xffffffffu, gu1i, 4);
    const float W0r = a2r * gu0r - a2i * gu0i - (b2r * gu1r + b2i * gu1i);
    const float W0i = a2r * gu0i + a2i * gu0r - (b2i * gu1r - b2r * gu1i);
    const float W1r = -(b2r * gu0r + b2i * gu0i + a2r * gu1r - a2i * gu1i);
    const float W1i = -(b2r * gu0i - b2i * gu0r - a2r * gu1i - a2i * gu1r);

    // ---- Product state: amp[i] = prod_w Wcol0_w[bit_w(i)] ----
    // Gather both column entries of each wire's W from lane w (independent
    // shfls), select by this amp's bit, multiply as a 2-level tree.
    float cr[4], ci[4];
    #pragma unroll
    for (int w = 0; w < 4; w++) {
        const float t0r = __shfl_sync(0xffffffffu, W0r, w);
        const float t0i = __shfl_sync(0xffffffffu, W0i, w);
        const float t1r = __shfl_sync(0xffffffffu, W1r, w);
        const float t1i = __shfl_sync(0xffffffffu, W1i, w);
        const bool b = (amp >> (3 - w)) & 1;
        cr[w] = b ? t1r : t0r;
        ci[w] = b ? t1i : t0i;
    }
    // (c0*c1) and (c2*c3) in parallel, then combine
    const float p01r = cr[0] * cr[1] - ci[0] * ci[1];
    const float p01i = cr[0] * ci[1] + ci[0] * cr[1];
    const float p23r = cr[2] * cr[3] - ci[2] * ci[3];
    const float p23i = cr[2] * ci[3] + ci[2] * cr[3];
    float sr = p01r * p23r - p01i * p23i;
    float si = p01r * p23i + p01i * p23r;

#define GATE(g, w) {                                                         \
    const int s_ = 8 >> (w);                                                 \
    const float u0r = __shfl_sync(0xffffffffu, gu0r, (g));                   \
    const float u0i = __shfl_sync(0xffffffffu, gu0i, (g));                   \
    const float u1r = __shfl_sync(0xffffffffu, gu1r, (g));                   \
    const float u1i = __shfl_sync(0xffffffffu, gu1i, (g));                   \
    const float sgn = (lane & s_) ? -1.f : 1.f;                              \
    const float Ai = sgn * u0i, Br = sgn * u1r;                              \
    const float pr = __shfl_xor_sync(0xffffffffu, sr, s_);                   \
    const float pi = __shfl_xor_sync(0xffffffffu, si, s_);                   \
    const float nr = u0r * sr - Ai * si + Br * pr - u1i * pi;                \
    const float ni = u0r * si + Ai * sr + Br * pi + u1i * pr;                \
    sr = nr; si = ni; }

#define CNOT(w) {                                                            \
    const int sc_ = 8 >> (w), sg_ = 4 >> (w);                                \
    const float pr = __shfl_xor_sync(0xffffffffu, sr, sg_);                  \
    const float pi = __shfl_xor_sync(0xffffffffu, si, sg_);                  \
    if (lane & sc_) { sr = pr; si = pi; } }

    // layer-0 CNOT chain (must act on state; layer-1 gates follow)
    CNOT(0) CNOT(1) CNOT(2)
    // layer-1 rotations (slots 8..11)
    GATE(8, 0) GATE(9, 1) GATE(10, 2) GATE(11, 3)
    // layer-1 CNOT chain: folded into coef above — nothing to do here.

#undef GATE
#undef CNOT

    // ---- logit sum: butterfly over 16-lane halves; both halves mirrored,
    //      so EVERY lane ends with the full sum (no broadcast needed) ----
    float val = (sr * sr + si * si) * coef;
    val += __shfl_xor_sync(0xffffffffu, val, 1);
    val += __shfl_xor_sync(0xffffffffu, val, 2);
    val += __shfl_xor_sync(0xffffffffu, val, 4);
    val += __shfl_xor_sync(0xffffffffu, val, 8);

    const float p = 1.f / (1.f + __expf(-(bias + val)));
    const float q = 1.f - p;
    const float4 v = make_float4(p, q, p, q);

    // ---- Each thread stores its own output slice immediately ----
    for (int i = tid; i < n4; i += blockDim.x) {
        out4[i] = v;
    }
}

extern "C" void kernel_launch(void* const* d_in, const int* in_sizes, int n_in,
                              void* d_out, int out_size) {
    // metadata order: 0=x 1=conv1_w 2=conv1_b 3=conv2_w 4=conv2_b 5=fc1_w
    //                 6=fc1_b 7=fc2_w 8=fc2_b 9=q_params 10=q_basis 11=fc3_w 12=fc3_b
    const float* q_params = (const float*)d_in[9];
    const float* q_basis  = (const float*)d_in[10];
    const float* fc3_w    = (const float*)d_in[11];
    const float* fc3_b    = (const float*)d_in[12];
    float4* out4 = (float4*)d_out;
    const int n4 = out_size / 4;   // out_size = B*2 floats; 4 floats per float4

    qhbc_kernel<<<1, 512>>>(q_params, q_basis, fc3_w, fc3_b, out4, n4);
}